// round 8
// baseline (speedup 1.0000x reference)
#include <cuda_runtime.h>
#include <cstdint>

// LocalAggregationLoss — bucket-sorted gather for DRAM locality.
//   K1: normalize codes -> g_v; zero counters/accumulators
//   K2: scatter all 409600 (row, meta) gather requests into row-buckets
//   K3: warp-per-bucket: gather rows in near-sorted address order, dot with
//       v_b (L2-resident table), exp, atomic-accumulate into g_acc[meta]
//   K4: out[b] = log(acc[2b]) - log(acc[2b+1])

#define DIM    128
#define KNEI   200
#define NB     1024
#define TINV   (1.0f / 0.07f)
#define HALF   (NB * KNEI)        // 204800
#define TOTE   (2 * HALF)         // 409600
#define NBUCK  8192
#define BSHIFT 7                  // bucket = row >> 7 (64KB region)
#define CAP    112                // Poisson(50) overflow prob ~1e-17/bucket
#define N_BANK 1000000LL

__device__ uint32_t g_cnt[NBUCK];
__device__ uint2    g_ent[NBUCK * CAP];     // {byte_off, meta}
__device__ float    g_v[NB * DIM];          // normalized codes (512 KB)
__device__ float    g_acc[2 * NB];
__device__ uint2    g_ovf[8192];
__device__ uint32_t g_ovfcnt;

// int64 vs int32 detection: first 16B as two int64 must both be in [0,1e6).
__device__ __forceinline__ bool idx_is64(const void* p)
{
    const longlong2 v = *reinterpret_cast<const longlong2*>(p);
    return (v.x >= 0 && v.x < N_BANK) & (v.y >= 0 && v.y < N_BANK);
}

// ---------------- K1: normalize codes + zero scratch ----------------
__global__ __launch_bounds__(128)
void k1_init(const float* __restrict__ codes)
{
    const int b    = blockIdx.x;
    const int tid  = threadIdx.x;
    const int wid  = tid >> 5;
    const int lane = tid & 31;
    __shared__ float red[4];

    float c = codes[b * DIM + tid];
    float ss = c * c;
    #pragma unroll
    for (int o = 16; o; o >>= 1) ss += __shfl_xor_sync(0xffffffffu, ss, o);
    if (lane == 0) red[wid] = ss;
    __syncthreads();
    const float inv_norm = rsqrtf(red[0] + red[1] + red[2] + red[3]);
    g_v[b * DIM + tid] = c * inv_norm;

    if (tid < 8)  g_cnt[b * 8 + tid] = 0;
    if (tid < 2)  g_acc[b * 2 + tid] = 0.0f;
    if (b == 0 && tid == 0) g_ovfcnt = 0;
}

// ---------------- K2: scatter requests into buckets ----------------
__global__ __launch_bounds__(256)
void k2_scatter(const void* __restrict__ idx_bg,
                const void* __restrict__ idx_cl)
{
    const int gid = blockIdx.x * 256 + threadIdx.x;
    if (gid >= TOTE) return;

    const int  side = gid >= HALF;
    const int  r    = gid - side * HALF;      // 0..204799
    const bool is64 = idx_is64(idx_bg);
    const void* arr = side ? idx_cl : idx_bg;

    uint32_t row;
    if (is64) row = (uint32_t)((const long long*)arr)[r];
    else      row = (uint32_t)((const int*)arr)[r];

    const uint32_t meta   = (uint32_t)(r / KNEI) * 2u + (uint32_t)side;
    const uint32_t bucket = row >> BSHIFT;
    const uint32_t pos    = atomicAdd(&g_cnt[bucket], 1u);
    const uint2    e      = make_uint2(row * 512u, meta);
    if (pos < CAP) g_ent[bucket * CAP + pos] = e;
    else           g_ovf[atomicAdd(&g_ovfcnt, 1u) & 8191u] = e;
}

// ---------------- K3: warp-per-bucket gather + dot + exp ----------------
__device__ __forceinline__ void process_entry(const char* gb, uint32_t off,
                                              uint32_t meta, int lane)
{
    const float4 a = __ldg(reinterpret_cast<const float4*>(gb + off));
    const float4 w = __ldg(reinterpret_cast<const float4*>(
        reinterpret_cast<const char*>(g_v) + (meta >> 1) * 512u + lane * 16));
    float d = a.x * w.x + a.y * w.y + a.z * w.z + a.w * w.w;
    #pragma unroll
    for (int o = 16; o; o >>= 1) d += __shfl_xor_sync(0xffffffffu, d, o);
    if (lane == 0) atomicAdd(&g_acc[meta], __expf(d * TINV));
}

__global__ __launch_bounds__(128, 7)
void k3_gather(const float* __restrict__ bank)
{
    const int tid  = threadIdx.x;
    const int wid  = tid >> 5;
    const int lane = tid & 31;
    const int bk   = blockIdx.x * 4 + wid;

    const int n    = min((int)g_cnt[bk], CAP);
    const int base = bk * CAP;
    const char* gb = reinterpret_cast<const char*>(bank) + lane * 16;

    int t = 0;
    for (; t + 5 <= n; t += 5) {
        uint2 e = (lane < 5) ? g_ent[base + t + lane] : make_uint2(0u, 0u);
        uint32_t off[5], mt[5];
        #pragma unroll
        for (int u = 0; u < 5; ++u) {
            off[u] = __shfl_sync(0xffffffffu, e.x, u);
            mt[u]  = __shfl_sync(0xffffffffu, e.y, u);
        }
        float4 a[5], w[5];
        #pragma unroll
        for (int u = 0; u < 5; ++u) {          // 10 loads in flight
            a[u] = __ldg(reinterpret_cast<const float4*>(gb + off[u]));
            w[u] = __ldg(reinterpret_cast<const float4*>(
                reinterpret_cast<const char*>(g_v)
                + (mt[u] >> 1) * 512u + lane * 16));
        }
        #pragma unroll
        for (int u = 0; u < 5; ++u) {
            float d = a[u].x * w[u].x + a[u].y * w[u].y
                    + a[u].z * w[u].z + a[u].w * w[u].w;
            #pragma unroll
            for (int o = 16; o; o >>= 1)
                d += __shfl_xor_sync(0xffffffffu, d, o);
            if (lane == 0) atomicAdd(&g_acc[mt[u]], __expf(d * TINV));
        }
    }
    for (; t < n; ++t) {                       // remainder
        uint2 e = (lane == 0) ? g_ent[base + t] : make_uint2(0u, 0u);
        const uint32_t off = __shfl_sync(0xffffffffu, e.x, 0);
        const uint32_t mt  = __shfl_sync(0xffffffffu, e.y, 0);
        process_entry(gb, off, mt, lane);
    }

    // overflow entries (normally zero)
    if (blockIdx.x == 0 && wid == 0) {
        const int m = (int)min(g_ovfcnt, 8192u);
        for (int i = 0; i < m; ++i) {
            uint2 e = (lane == 0) ? g_ovf[i] : make_uint2(0u, 0u);
            const uint32_t off = __shfl_sync(0xffffffffu, e.x, 0);
            const uint32_t mt  = __shfl_sync(0xffffffffu, e.y, 0);
            process_entry(gb, off, mt, lane);
        }
    }
}

// ---------------- K4: finalize ----------------
__global__ __launch_bounds__(128)
void k4_final(float* __restrict__ out)
{
    const int b = blockIdx.x * 128 + threadIdx.x;
    if (b < NB)
        out[b] = __logf(g_acc[2 * b]) - __logf(g_acc[2 * b + 1]);
}

extern "C" void kernel_launch(void* const* d_in, const int* in_sizes, int n_in,
                              void* d_out, int out_size)
{
    const float* codes  = (const float*)d_in[0];
    const float* bank   = (const float*)d_in[1];
    const void*  idx_bg = d_in[2];
    const void*  idx_cl = d_in[3];
    float*       out    = (float*)d_out;

    k1_init<<<NB, 128>>>(codes);
    k2_scatter<<<(TOTE + 255) / 256, 256>>>(idx_bg, idx_cl);
    k3_gather<<<NBUCK / 4, 128>>>(bank);
    k4_final<<<(NB + 127) / 128, 128>>>(out);
}

// round 10
// speedup vs baseline: 2.0392x; 2.0392x over previous
#include <cuda_runtime.h>
#include <cstdint>

// LocalAggregationLoss — 256-bit gathers (LDG.E.256) with L2::evict_last.
// One load instruction per row-pair: lanes 0-15 cover the background row,
// lanes 16-31 the close row (32B per lane).
//   codes:        [1024, 128] fp32
//   memory_bank:  [1000000, 128] fp32
//   idx_background, idx_close: [1024, 200] int32 (JAX default) or int64
//   out[b] = log(sum_k exp(dot(bank[idx_bg[b,k]], v_b)/T))
//          - log(sum_k exp(dot(bank[idx_cl[b,k]], v_b)/T))

#define DIM    128
#define KNEI   200
#define TINV   (1.0f / 0.07f)
#define NWARP  4
#define RPW    (KNEI / NWARP)   // 50 row-pairs per warp
#define BATCH5 5                 // pairs per batch (5 LDG.256 in flight)
#define NBATCH (RPW / BATCH5)
#define N_BANK 1000000LL

// int64 vs int32 detection: first 16B as two int64 must both be in [0,1e6).
__device__ __forceinline__ bool idx_is64(const void* p)
{
    const longlong2 v = *reinterpret_cast<const longlong2*>(p);
    return (v.x >= 0 && v.x < N_BANK) & (v.y >= 0 && v.y < N_BANK);
}

struct F8 { float f[8]; };

// 32B gather with L2 evict_last (only legal on v8.b32 / v4.b64 on sm_103a).
__device__ __forceinline__ F8 ldg256_el(const void* p)
{
    uint32_t r0,r1,r2,r3,r4,r5,r6,r7;
    asm volatile(
        "ld.global.nc.L2::evict_last.v8.b32 {%0,%1,%2,%3,%4,%5,%6,%7}, [%8];"
        : "=r"(r0),"=r"(r1),"=r"(r2),"=r"(r3),
          "=r"(r4),"=r"(r5),"=r"(r6),"=r"(r7)
        : "l"(p));
    F8 x;
    x.f[0]=__uint_as_float(r0); x.f[1]=__uint_as_float(r1);
    x.f[2]=__uint_as_float(r2); x.f[3]=__uint_as_float(r3);
    x.f[4]=__uint_as_float(r4); x.f[5]=__uint_as_float(r5);
    x.f[6]=__uint_as_float(r6); x.f[7]=__uint_as_float(r7);
    return x;
}

__global__ __launch_bounds__(NWARP * 32, 7)
void la_loss_kernel(const float* __restrict__ codes,
                    const float* __restrict__ bank,
                    const void*  __restrict__ idx_bg,
                    const void*  __restrict__ idx_cl,
                    float* __restrict__ out)
{
    const int b    = blockIdx.x;
    const int tid  = threadIdx.x;
    const int wid  = tid >> 5;
    const int lane = tid & 31;
    const int hl   = lane & 15;          // lane within half-warp

    __shared__ float v_sh[DIM];
    __shared__ float red[NWARP];
    __shared__ float s1_sh[NWARP];
    __shared__ float s2_sh[NWARP];
    __shared__ uint32_t off_sh[NWARP][2][RPW];

    // ---- normalize code row (128 threads = 128 elements) ----
    float c = codes[b * DIM + tid];
    float ss = c * c;
    #pragma unroll
    for (int o = 16; o; o >>= 1) ss += __shfl_xor_sync(0xffffffffu, ss, o);
    if (lane == 0) red[wid] = ss;
    __syncthreads();
    float total = 0.0f;
    #pragma unroll
    for (int w = 0; w < NWARP; ++w) total += red[w];
    const float inv_norm = rsqrtf(total);
    v_sh[tid] = c * inv_norm;

    // ---- stage this warp's 50+50 indices as u32 byte offsets ----
    const long long base = (long long)b * KNEI + wid * RPW;
    if (idx_is64(idx_bg)) {
        const long long* ibg = (const long long*)idx_bg + base;
        const long long* icl = (const long long*)idx_cl + base;
        #pragma unroll
        for (int r = lane; r < RPW; r += 32) {
            off_sh[wid][0][r] = (uint32_t)ibg[r] * 512u;
            off_sh[wid][1][r] = (uint32_t)icl[r] * 512u;
        }
    } else {
        const int* ibg = (const int*)idx_bg + base;
        const int* icl = (const int*)idx_cl + base;
        #pragma unroll
        for (int r = lane; r < RPW; r += 32) {
            off_sh[wid][0][r] = (uint32_t)ibg[r] * 512u;
            off_sh[wid][1][r] = (uint32_t)icl[r] * 512u;
        }
    }
    __syncthreads();

    // each lane's 8 v-components (half-warp covers the full 128-dim vector)
    float vr[8];
    #pragma unroll
    for (int i = 0; i < 8; ++i) vr[i] = v_sh[hl * 8 + i];

    // lanes 0-15 read the bg row, 16-31 the cl row
    const int  side  = lane >> 4;
    const char* gb   = reinterpret_cast<const char*>(bank)
                     + (uint32_t)(hl * 32);

    float s1 = 0.0f, s2 = 0.0f;

    #pragma unroll 1
    for (int t = 0; t < NBATCH; ++t) {
        F8 a[BATCH5];

        // 5 LDG.256 in flight: 5 KB per warp outstanding
        #pragma unroll
        for (int u = 0; u < BATCH5; ++u) {
            const uint32_t o = off_sh[wid][side][t * BATCH5 + u];
            a[u] = ldg256_el(gb + o);
        }

        #pragma unroll
        for (int u = 0; u < BATCH5; ++u) {
            float d = a[u].f[0] * vr[0] + a[u].f[1] * vr[1]
                    + a[u].f[2] * vr[2] + a[u].f[3] * vr[3]
                    + a[u].f[4] * vr[4] + a[u].f[5] * vr[5]
                    + a[u].f[6] * vr[6] + a[u].f[7] * vr[7];
            // reduce within each 16-lane half-warp
            #pragma unroll
            for (int o = 8; o; o >>= 1)
                d += __shfl_xor_sync(0xffffffffu, d, o);
            const float d1 = __shfl_sync(0xffffffffu, d, 0);
            const float d2 = __shfl_sync(0xffffffffu, d, 16);
            s1 += __expf(d1 * TINV);
            s2 += __expf(d2 * TINV);
        }
    }

    if (lane == 0) { s1_sh[wid] = s1; s2_sh[wid] = s2; }
    __syncthreads();

    if (tid == 0) {
        float S1 = 0.0f, S2 = 0.0f;
        #pragma unroll
        for (int w = 0; w < NWARP; ++w) { S1 += s1_sh[w]; S2 += s2_sh[w]; }
        out[b] = __logf(S1) - __logf(S2);
    }
}

extern "C" void kernel_launch(void* const* d_in, const int* in_sizes, int n_in,
                              void* d_out, int out_size)
{
    const float* codes  = (const float*)d_in[0];
    const float* bank   = (const float*)d_in[1];
    const void*  idx_bg = d_in[2];
    const void*  idx_cl = d_in[3];
    float*       out    = (float*)d_out;

    la_loss_kernel<<<1024, NWARP * 32>>>(codes, bank, idx_bg, idx_cl, out);
}